// round 8
// baseline (speedup 1.0000x reference)
#include <cuda_runtime.h>
#include <cstdint>

// ---------------------------------------------------------------------------
// Problem constants (shapes fixed by the dataset; N,E taken from in_sizes)
// ---------------------------------------------------------------------------
#define NMAX 100000
#define PDIM 128

// Scratch (device globals: allocation-free per harness rules)
__device__ float g_mu  [NMAX * PDIM];   // mu  [N,128]
__device__ float g_nb  [NMAX * PDIM];   // nb_sum [N,128] (atomics)
__device__ float g_mup [NMAX * PDIM];   // mu' [N,128]
__device__ float g_deg [NMAX];
__device__ float g_inv [NMAX];          // 1/||x_v||
__device__ float g_summu[PDIM];
__device__ float g_B2 [128 * 128];      // theta2^T  (Bt[k][p])
__device__ float g_B5 [128 * 128];      // theta5^T
__device__ float g_Bh [256 * 128];      // h_theta^T
__device__ float g_cup;                 // scalar shared "up" contribution

// ---------------------------------------------------------------------------
// f32x2 packed-FMA helpers (Blackwell packed fp32 path: 2x FFMA throughput)
// ---------------------------------------------------------------------------
__device__ __forceinline__ unsigned long long pk2(float x, float y) {
    unsigned long long r;
    asm("mov.b64 %0, {%1, %2};" : "=l"(r) : "f"(x), "f"(y));
    return r;
}
__device__ __forceinline__ void fma2(unsigned long long& c,
                                     unsigned long long a,
                                     unsigned long long b) {
    asm("fma.rn.f32x2 %0, %1, %2, %0;" : "+l"(c) : "l"(a), "l"(b));
}
__device__ __forceinline__ float2 up2(unsigned long long v) {
    float2 r;
    asm("mov.b64 {%0, %1}, %2;" : "=f"(r.x), "=f"(r.y) : "l"(v));
    return r;
}

// ---------------------------------------------------------------------------
// prep: transpose the small weight matrices once per call; zero sum_mu'
// ---------------------------------------------------------------------------
__global__ void prep_kernel(const float* __restrict__ th2,
                            const float* __restrict__ th5,
                            const float* __restrict__ hth) {
    int idx = blockIdx.x * blockDim.x + threadIdx.x;
    int stride = gridDim.x * blockDim.x;
    for (int i = idx; i < 128 * 128; i += stride) {
        int k = i >> 7, p = i & 127;
        g_B2[i] = th2[p * 128 + k];
        g_B5[i] = th5[p * 128 + k];
    }
    for (int i = idx; i < 256 * 128; i += stride) {
        int k = i >> 7, p = i & 127;
        g_Bh[i] = hth[p * 256 + k];
    }
    if (idx < PDIM) g_summu[idx] = 0.0f;
}

// zero nb_sum and deg
__global__ void zero_kernel(int N) {
    int idx = blockIdx.x * blockDim.x + threadIdx.x;
    int stride = gridDim.x * blockDim.x;
    int n4 = N * 32;  // N*128 floats as float4
    float4 z = make_float4(0.f, 0.f, 0.f, 0.f);
    float4* nb4 = reinterpret_cast<float4*>(g_nb);
    for (int i = idx; i < n4; i += stride) nb4[i] = z;
    for (int i = idx; i < N; i += stride) g_deg[i] = 0.0f;
}

// per-node inverse row norm of x (one warp per node)
__global__ void norm_kernel(const float* __restrict__ x, int N) {
    int warp = (blockIdx.x * blockDim.x + threadIdx.x) >> 5;
    int lane = threadIdx.x & 31;
    if (warp >= N) return;
    float4 v = reinterpret_cast<const float4*>(x + (size_t)warp * 128)[lane];
    float s = v.x * v.x + v.y * v.y + v.z * v.z + v.w * v.w;
    #pragma unroll
    for (int o = 16; o; o >>= 1) s += __shfl_xor_sync(0xFFFFFFFFu, s, o);
    if (lane == 0) g_inv[warp] = (s > 0.0f) ? rsqrtf(s) : 1.0f;
}

// ---------------------------------------------------------------------------
// Edge aggregation: nb_sum[src] += mu[dst]; deg[src] += 1   (warp per edge)
// ---------------------------------------------------------------------------
__global__ void edge_kernel(const int* __restrict__ src,
                            const int* __restrict__ dst, int E) {
    int lane = threadIdx.x & 31;
    int warp = (blockIdx.x * blockDim.x + threadIdx.x) >> 5;
    int nwarps = (gridDim.x * blockDim.x) >> 5;
    for (int e = warp; e < E; e += nwarps) {
        int s = __ldg(src + e);
        int d = __ldg(dst + e);
        float4 v = __ldg(reinterpret_cast<const float4*>(g_mu + (size_t)d * 128) + lane);
        float* p = g_nb + (size_t)s * 128 + lane * 4;
        asm volatile("red.global.add.v4.f32 [%0], {%1, %2, %3, %4};"
                     :: "l"(p), "f"(v.x), "f"(v.y), "f"(v.z), "f"(v.w)
                     : "memory");
        if (lane == 0) atomicAdd(g_deg + s, 1.0f);
    }
}

// ---------------------------------------------------------------------------
// GEMM core: 128x128 tile, 256 threads, 8x8/thread, f32x2 packed accumulators
// smem: As [k][i] (transposed, 128x128) + Bs [k][j] (128x128) = 128 KB
// ---------------------------------------------------------------------------
__device__ __forceinline__ void load_B(float* Bs, const float* __restrict__ Bt,
                                       int kBase, int tid) {
    const float4* srcp = reinterpret_cast<const float4*>(Bt + (size_t)kBase * 128);
    float4* dstp = reinterpret_cast<float4*>(Bs);
    #pragma unroll
    for (int r = 0; r < 16; ++r) dstp[tid + 256 * r] = srcp[tid + 256 * r];
}

__device__ __forceinline__ void mma128(const float* As, const float* Bs,
                                       int row0, int col0,
                                       unsigned long long (&acc)[8][4]) {
    #pragma unroll 2
    for (int k = 0; k < 128; ++k) {
        float4 a0 = *reinterpret_cast<const float4*>(As + k * 128 + row0);
        float4 a1 = *reinterpret_cast<const float4*>(As + k * 128 + row0 + 4);
        float4 b0 = *reinterpret_cast<const float4*>(Bs + k * 128 + col0);
        float4 b1 = *reinterpret_cast<const float4*>(Bs + k * 128 + col0 + 4);
        unsigned long long bp[4] = { pk2(b0.x, b0.y), pk2(b0.z, b0.w),
                                     pk2(b1.x, b1.y), pk2(b1.z, b1.w) };
        float av[8] = { a0.x, a0.y, a0.z, a0.w, a1.x, a1.y, a1.z, a1.w };
        #pragma unroll
        for (int i = 0; i < 8; ++i) {
            unsigned long long ap = pk2(av[i], av[i]);
            #pragma unroll
            for (int j = 0; j < 4; ++j) fma2(acc[i][j], ap, bp[j]);
        }
    }
}

// ---------------------------------------------------------------------------
// Stage A: mu = relu(xn @ theta2^T + conn @ theta1^T)
// ---------------------------------------------------------------------------
__global__ void __launch_bounds__(256)
mu_kernel(const float* __restrict__ x, const float* __restrict__ sv,
          const float* __restrict__ tv, const float* __restrict__ th1, int N) {
    extern __shared__ float sm[];
    float* As = sm;
    float* Bs = sm + 128 * 128;
    int tid = threadIdx.x;
    int lane = tid & 31, w = tid >> 5;
    int rowBase = blockIdx.x * 128;

    // A load: x row scaled by inv-norm, stored transposed As[k][i]
    #pragma unroll
    for (int rb = 0; rb < 4; ++rb) {
        int r = rb * 32 + lane;
        int gr = rowBase + r;
        bool ok = gr < N;
        float sc = ok ? g_inv[gr] : 0.0f;
        #pragma unroll
        for (int cc = 0; cc < 4; ++cc) {
            int k4 = w + 8 * cc;
            float4 v = ok ? __ldg(reinterpret_cast<const float4*>(x + (size_t)gr * 128) + k4)
                          : make_float4(0.f, 0.f, 0.f, 0.f);
            int kb = k4 * 4;
            As[(kb + 0) * 128 + r] = v.x * sc;
            As[(kb + 1) * 128 + r] = v.y * sc;
            As[(kb + 2) * 128 + r] = v.z * sc;
            As[(kb + 3) * 128 + r] = v.w * sc;
        }
    }
    load_B(Bs, g_B2, 0, tid);
    __syncthreads();

    unsigned long long acc[8][4] = {};
    int row0 = (tid >> 4) * 8, col0 = (tid & 15) * 8;
    mma128(As, Bs, row0, col0, acc);

    // epilogue: + conn term, relu, store
    #pragma unroll
    for (int i = 0; i < 8; ++i) {
        int gr = rowBase + row0 + i;
        if (gr >= N) continue;
        float s1 = __ldg(sv + gr), t1 = __ldg(tv + gr);
        float o[8];
        #pragma unroll
        for (int j = 0; j < 4; ++j) {
            float2 v = up2(acc[i][j]);
            o[2 * j] = v.x; o[2 * j + 1] = v.y;
        }
        #pragma unroll
        for (int jj = 0; jj < 8; ++jj) {
            int col = col0 + jj;
            float c = o[jj] + s1 * __ldg(th1 + col * 2) + t1 * __ldg(th1 + col * 2 + 1);
            o[jj] = fmaxf(c, 0.0f);
        }
        float4* dp = reinterpret_cast<float4*>(g_mu + (size_t)gr * 128 + col0);
        dp[0] = make_float4(o[0], o[1], o[2], o[3]);
        dp[1] = make_float4(o[4], o[5], o[6], o[7]);
    }
}

// ---------------------------------------------------------------------------
// Stage C: mu' = [mu ; relu(deg*mu - nb)] @ h_theta^T   (K=256, two chunks)
//          also accumulates column sums into g_summu
// ---------------------------------------------------------------------------
__global__ void __launch_bounds__(256)
mup_kernel(int N) {
    extern __shared__ float sm[];
    float* As = sm;
    float* Bs = sm + 128 * 128;
    int tid = threadIdx.x;
    int lane = tid & 31, w = tid >> 5;
    int rowBase = blockIdx.x * 128;
    int row0 = (tid >> 4) * 8, col0 = (tid & 15) * 8;
    unsigned long long acc[8][4] = {};

    // chunk 0: A = mu
    #pragma unroll
    for (int rb = 0; rb < 4; ++rb) {
        int r = rb * 32 + lane;
        int gr = rowBase + r;
        bool ok = gr < N;
        #pragma unroll
        for (int cc = 0; cc < 4; ++cc) {
            int k4 = w + 8 * cc;
            float4 v = ok ? __ldg(reinterpret_cast<const float4*>(g_mu + (size_t)gr * 128) + k4)
                          : make_float4(0.f, 0.f, 0.f, 0.f);
            int kb = k4 * 4;
            As[(kb + 0) * 128 + r] = v.x;
            As[(kb + 1) * 128 + r] = v.y;
            As[(kb + 2) * 128 + r] = v.z;
            As[(kb + 3) * 128 + r] = v.w;
        }
    }
    load_B(Bs, g_Bh, 0, tid);
    __syncthreads();
    mma128(As, Bs, row0, col0, acc);
    __syncthreads();

    // chunk 1: A = relu(deg*mu - nb)
    #pragma unroll
    for (int rb = 0; rb < 4; ++rb) {
        int r = rb * 32 + lane;
        int gr = rowBase + r;
        bool ok = gr < N;
        float dg = ok ? g_deg[gr] : 0.0f;
        #pragma unroll
        for (int cc = 0; cc < 4; ++cc) {
            int k4 = w + 8 * cc;
            float4 m = ok ? __ldg(reinterpret_cast<const float4*>(g_mu + (size_t)gr * 128) + k4)
                          : make_float4(0.f, 0.f, 0.f, 0.f);
            float4 nb = ok ? __ldg(reinterpret_cast<const float4*>(g_nb + (size_t)gr * 128) + k4)
                           : make_float4(0.f, 0.f, 0.f, 0.f);
            int kb = k4 * 4;
            As[(kb + 0) * 128 + r] = fmaxf(dg * m.x - nb.x, 0.0f);
            As[(kb + 1) * 128 + r] = fmaxf(dg * m.y - nb.y, 0.0f);
            As[(kb + 2) * 128 + r] = fmaxf(dg * m.z - nb.z, 0.0f);
            As[(kb + 3) * 128 + r] = fmaxf(dg * m.w - nb.w, 0.0f);
        }
    }
    load_B(Bs, g_Bh, 128, tid);
    __syncthreads();
    mma128(As, Bs, row0, col0, acc);
    __syncthreads();  // smem free for reduction reuse

    // epilogue: store mu' and reduce column sums
    float colp[8] = {0.f, 0.f, 0.f, 0.f, 0.f, 0.f, 0.f, 0.f};
    #pragma unroll
    for (int i = 0; i < 8; ++i) {
        int gr = rowBase + row0 + i;
        float o[8];
        #pragma unroll
        for (int j = 0; j < 4; ++j) {
            float2 v = up2(acc[i][j]);
            o[2 * j] = v.x; o[2 * j + 1] = v.y;
        }
        #pragma unroll
        for (int jj = 0; jj < 8; ++jj) colp[jj] += o[jj];  // padded rows are 0
        if (gr < N) {
            float4* dp = reinterpret_cast<float4*>(g_mup + (size_t)gr * 128 + col0);
            dp[0] = make_float4(o[0], o[1], o[2], o[3]);
            dp[1] = make_float4(o[4], o[5], o[6], o[7]);
        }
    }
    float* part = sm;  // reuse As region: 16 x 128
    int ty = tid >> 4;
    #pragma unroll
    for (int jj = 0; jj < 8; ++jj) part[ty * 128 + col0 + jj] = colp[jj];
    __syncthreads();
    if (tid < 128) {
        float s = 0.0f;
        #pragma unroll
        for (int t = 0; t < 16; ++t) s += part[t * 128 + tid];
        atomicAdd(&g_summu[tid], s);
    }
}

// ---------------------------------------------------------------------------
// Q head: c_up = sum_p relu((theta4 @ sum_mu')[p]) * theta3[p]   (one block)
// ---------------------------------------------------------------------------
__global__ void qhead_kernel(const float* __restrict__ th4,
                             const float* __restrict__ th3) {
    __shared__ float svv[128];
    __shared__ float rbuf[4];
    int tid = threadIdx.x;
    svv[tid] = g_summu[tid];
    __syncthreads();
    float up = 0.0f;
    #pragma unroll 4
    for (int q = 0; q < 128; ++q) up += th4[tid * 128 + q] * svv[q];
    float v = fmaxf(up, 0.0f) * th3[tid];
    #pragma unroll
    for (int o = 16; o; o >>= 1) v += __shfl_xor_sync(0xFFFFFFFFu, v, o);
    if ((tid & 31) == 0) rbuf[tid >> 5] = v;
    __syncthreads();
    if (tid == 0) g_cup = rbuf[0] + rbuf[1] + rbuf[2] + rbuf[3];
}

// ---------------------------------------------------------------------------
// Stage E: out[v] = c_up + sum_j relu((mu' @ theta5^T)[v,j]) * theta3[128+j]
// ---------------------------------------------------------------------------
__global__ void __launch_bounds__(256)
out_kernel(const float* __restrict__ th3, float* __restrict__ out, int N) {
    extern __shared__ float sm[];
    float* As = sm;
    float* Bs = sm + 128 * 128;
    int tid = threadIdx.x;
    int lane = tid & 31, w = tid >> 5;
    int rowBase = blockIdx.x * 128;

    #pragma unroll
    for (int rb = 0; rb < 4; ++rb) {
        int r = rb * 32 + lane;
        int gr = rowBase + r;
        bool ok = gr < N;
        #pragma unroll
        for (int cc = 0; cc < 4; ++cc) {
            int k4 = w + 8 * cc;
            float4 v = ok ? __ldg(reinterpret_cast<const float4*>(g_mup + (size_t)gr * 128) + k4)
                          : make_float4(0.f, 0.f, 0.f, 0.f);
            int kb = k4 * 4;
            As[(kb + 0) * 128 + r] = v.x;
            As[(kb + 1) * 128 + r] = v.y;
            As[(kb + 2) * 128 + r] = v.z;
            As[(kb + 3) * 128 + r] = v.w;
        }
    }
    load_B(Bs, g_B5, 0, tid);
    __syncthreads();

    unsigned long long acc[8][4] = {};
    int row0 = (tid >> 4) * 8, col0 = (tid & 15) * 8;
    mma128(As, Bs, row0, col0, acc);
    __syncthreads();  // smem free for reduction reuse

    // per-thread weighted relu row partials
    float rowp[8];
    #pragma unroll
    for (int i = 0; i < 8; ++i) {
        float rp = 0.0f;
        #pragma unroll
        for (int j = 0; j < 4; ++j) {
            float2 v = up2(acc[i][j]);
            rp += fmaxf(v.x, 0.0f) * __ldg(th3 + 128 + col0 + 2 * j);
            rp += fmaxf(v.y, 0.0f) * __ldg(th3 + 128 + col0 + 2 * j + 1);
        }
        rowp[i] = rp;
    }
    float* red = sm;  // 16 x 129 (conflict-free stride)
    int tx = tid & 15;
    #pragma unroll
    for (int i = 0; i < 8; ++i) red[tx * 129 + row0 + i] = rowp[i];
    __syncthreads();
    if (tid < 128) {
        float s = 0.0f;
        #pragma unroll
        for (int t = 0; t < 16; ++t) s += red[t * 129 + tid];
        int gr = rowBase + tid;
        if (gr < N) out[gr] = g_cup + s;
    }
}

// ---------------------------------------------------------------------------
// Launch
// ---------------------------------------------------------------------------
extern "C" void kernel_launch(void* const* d_in, const int* in_sizes, int n_in,
                              void* d_out, int out_size) {
    const float* s_v  = (const float*)d_in[0];
    const float* t_v  = (const float*)d_in[1];
    const float* x    = (const float*)d_in[2];
    const int*   esrc = (const int*)  d_in[3];
    const int*   edst = (const int*)  d_in[4];
    const float* th1  = (const float*)d_in[5];
    const float* th2  = (const float*)d_in[6];
    const float* th3  = (const float*)d_in[7];
    const float* th4  = (const float*)d_in[8];
    const float* th5  = (const float*)d_in[9];
    const float* hth  = (const float*)d_in[10];
    float* out = (float*)d_out;

    int N = in_sizes[0];
    int E = in_sizes[3];
    int tiles = (N + 127) / 128;
    int smem = 2 * 128 * 128 * (int)sizeof(float);  // 128 KB

    cudaFuncSetAttribute(mu_kernel,  cudaFuncAttributeMaxDynamicSharedMemorySize, smem);
    cudaFuncSetAttribute(mup_kernel, cudaFuncAttributeMaxDynamicSharedMemorySize, smem);
    cudaFuncSetAttribute(out_kernel, cudaFuncAttributeMaxDynamicSharedMemorySize, smem);

    prep_kernel<<<64, 256>>>(th2, th5, hth);
    zero_kernel<<<4096, 256>>>(N);
    norm_kernel<<<(N + 7) / 8, 256>>>(x, N);
    mu_kernel<<<tiles, 256, smem>>>(x, s_v, t_v, th1, N);
    edge_kernel<<<8192, 256>>>(esrc, edst, E);
    mup_kernel<<<tiles, 256, smem>>>(N);
    qhead_kernel<<<1, 128>>>(th4, th3);
    out_kernel<<<tiles, 256, smem>>>(th3, out, N);
}

// round 9
// speedup vs baseline: 1.0467x; 1.0467x over previous
#include <cuda_runtime.h>
#include <cstdint>

// ---------------------------------------------------------------------------
// Problem constants (shapes fixed by the dataset; N,E taken from in_sizes)
// ---------------------------------------------------------------------------
#define NMAX 100000
#define PDIM 128

// Scratch (device globals: allocation-free per harness rules)
__device__ float g_mu  [NMAX * PDIM];   // mu  [N,128]
__device__ float g_nb  [NMAX * PDIM];   // nb_sum [N,128] (atomics)
__device__ float g_mup [NMAX * PDIM];   // mu' [N,128]
__device__ float g_deg [NMAX];
__device__ float g_inv [NMAX];          // 1/||x_v||
__device__ float g_summu[PDIM];
__device__ float g_B2 [128 * 128];      // theta2^T  (Bt[k][p])
__device__ float g_B5 [128 * 128];      // theta5^T
__device__ float g_Bh [256 * 128];      // h_theta^T
__device__ float g_cup;                 // scalar shared "up" contribution

// ---------------------------------------------------------------------------
// f32x2 packed-FMA helpers (Blackwell packed fp32 path: 2x FFMA throughput)
// ---------------------------------------------------------------------------
__device__ __forceinline__ unsigned long long pk2(float x, float y) {
    unsigned long long r;
    asm("mov.b64 %0, {%1, %2};" : "=l"(r) : "f"(x), "f"(y));
    return r;
}
__device__ __forceinline__ void fma2(unsigned long long& c,
                                     unsigned long long a,
                                     unsigned long long b) {
    asm("fma.rn.f32x2 %0, %1, %2, %0;" : "+l"(c) : "l"(a), "l"(b));
}
__device__ __forceinline__ float2 up2(unsigned long long v) {
    float2 r;
    asm("mov.b64 {%0, %1}, %2;" : "=f"(r.x), "=f"(r.y) : "l"(v));
    return r;
}

// ---------------------------------------------------------------------------
// prep: transpose the small weight matrices once per call; zero sum_mu'
// ---------------------------------------------------------------------------
__global__ void prep_kernel(const float* __restrict__ th2,
                            const float* __restrict__ th5,
                            const float* __restrict__ hth) {
    int idx = blockIdx.x * blockDim.x + threadIdx.x;
    int stride = gridDim.x * blockDim.x;
    for (int i = idx; i < 128 * 128; i += stride) {
        int k = i >> 7, p = i & 127;
        g_B2[i] = th2[p * 128 + k];
        g_B5[i] = th5[p * 128 + k];
    }
    for (int i = idx; i < 256 * 128; i += stride) {
        int k = i >> 7, p = i & 127;
        g_Bh[i] = hth[p * 256 + k];
    }
    if (idx < PDIM) g_summu[idx] = 0.0f;
}

// zero nb_sum and deg
__global__ void zero_kernel(int N) {
    int idx = blockIdx.x * blockDim.x + threadIdx.x;
    int stride = gridDim.x * blockDim.x;
    int n4 = N * 32;  // N*128 floats as float4
    float4 z = make_float4(0.f, 0.f, 0.f, 0.f);
    float4* nb4 = reinterpret_cast<float4*>(g_nb);
    for (int i = idx; i < n4; i += stride) nb4[i] = z;
    for (int i = idx; i < N; i += stride) g_deg[i] = 0.0f;
}

// per-node inverse row norm of x (one warp per node)
__global__ void norm_kernel(const float* __restrict__ x, int N) {
    int warp = (blockIdx.x * blockDim.x + threadIdx.x) >> 5;
    int lane = threadIdx.x & 31;
    if (warp >= N) return;
    float4 v = reinterpret_cast<const float4*>(x + (size_t)warp * 128)[lane];
    float s = v.x * v.x + v.y * v.y + v.z * v.z + v.w * v.w;
    #pragma unroll
    for (int o = 16; o; o >>= 1) s += __shfl_xor_sync(0xFFFFFFFFu, s, o);
    if (lane == 0) g_inv[warp] = (s > 0.0f) ? rsqrtf(s) : 1.0f;
}

// ---------------------------------------------------------------------------
// Edge aggregation: nb_sum[src] += mu[dst]; deg[src] += 1   (warp per edge)
// ---------------------------------------------------------------------------
__global__ void edge_kernel(const int* __restrict__ src,
                            const int* __restrict__ dst, int E) {
    int lane = threadIdx.x & 31;
    int warp = (blockIdx.x * blockDim.x + threadIdx.x) >> 5;
    int nwarps = (gridDim.x * blockDim.x) >> 5;
    for (int e = warp; e < E; e += nwarps) {
        int s = __ldg(src + e);
        int d = __ldg(dst + e);
        float4 v = __ldg(reinterpret_cast<const float4*>(g_mu + (size_t)d * 128) + lane);
        float* p = g_nb + (size_t)s * 128 + lane * 4;
        asm volatile("red.global.add.v4.f32 [%0], {%1, %2, %3, %4};"
                     :: "l"(p), "f"(v.x), "f"(v.y), "f"(v.z), "f"(v.w)
                     : "memory");
        if (lane == 0) atomicAdd(g_deg + s, 1.0f);
    }
}

// ---------------------------------------------------------------------------
// GEMM core: 128x128 tile, 256 threads, 8x8/thread, f32x2 packed accumulators
// smem: As [k][i] (transposed, 128x128) + Bs [k][j] (128x128) = 128 KB
// ---------------------------------------------------------------------------
__device__ __forceinline__ void load_B(float* Bs, const float* __restrict__ Bt,
                                       int kBase, int tid) {
    const float4* srcp = reinterpret_cast<const float4*>(Bt + (size_t)kBase * 128);
    float4* dstp = reinterpret_cast<float4*>(Bs);
    #pragma unroll
    for (int r = 0; r < 16; ++r) dstp[tid + 256 * r] = srcp[tid + 256 * r];
}

__device__ __forceinline__ void mma128(const float* As, const float* Bs,
                                       int row0, int col0,
                                       unsigned long long (&acc)[8][4]) {
    #pragma unroll 2
    for (int k = 0; k < 128; ++k) {
        float4 a0 = *reinterpret_cast<const float4*>(As + k * 128 + row0);
        float4 a1 = *reinterpret_cast<const float4*>(As + k * 128 + row0 + 4);
        float4 b0 = *reinterpret_cast<const float4*>(Bs + k * 128 + col0);
        float4 b1 = *reinterpret_cast<const float4*>(Bs + k * 128 + col0 + 4);
        unsigned long long bp[4] = { pk2(b0.x, b0.y), pk2(b0.z, b0.w),
                                     pk2(b1.x, b1.y), pk2(b1.z, b1.w) };
        float av[8] = { a0.x, a0.y, a0.z, a0.w, a1.x, a1.y, a1.z, a1.w };
        #pragma unroll
        for (int i = 0; i < 8; ++i) {
            unsigned long long ap = pk2(av[i], av[i]);
            #pragma unroll
            for (int j = 0; j < 4; ++j) fma2(acc[i][j], ap, bp[j]);
        }
    }
}

// ---------------------------------------------------------------------------
// Stage A: mu = relu(xn @ theta2^T + conn @ theta1^T)
// ---------------------------------------------------------------------------
__global__ void __launch_bounds__(256)
mu_kernel(const float* __restrict__ x, const float* __restrict__ sv,
          const float* __restrict__ tv, const float* __restrict__ th1, int N) {
    extern __shared__ float sm[];
    float* As = sm;
    float* Bs = sm + 128 * 128;
    int tid = threadIdx.x;
    int lane = tid & 31, w = tid >> 5;
    int rowBase = blockIdx.x * 128;

    // A load: x row scaled by inv-norm, stored transposed As[k][i]
    #pragma unroll
    for (int rb = 0; rb < 4; ++rb) {
        int r = rb * 32 + lane;
        int gr = rowBase + r;
        bool ok = gr < N;
        float sc = ok ? g_inv[gr] : 0.0f;
        #pragma unroll
        for (int cc = 0; cc < 4; ++cc) {
            int k4 = w + 8 * cc;
            float4 v = ok ? __ldg(reinterpret_cast<const float4*>(x + (size_t)gr * 128) + k4)
                          : make_float4(0.f, 0.f, 0.f, 0.f);
            int kb = k4 * 4;
            As[(kb + 0) * 128 + r] = v.x * sc;
            As[(kb + 1) * 128 + r] = v.y * sc;
            As[(kb + 2) * 128 + r] = v.z * sc;
            As[(kb + 3) * 128 + r] = v.w * sc;
        }
    }
    load_B(Bs, g_B2, 0, tid);
    __syncthreads();

    unsigned long long acc[8][4] = {};
    int row0 = (tid >> 4) * 8, col0 = (tid & 15) * 8;
    mma128(As, Bs, row0, col0, acc);

    // epilogue: + conn term, relu, store
    #pragma unroll
    for (int i = 0; i < 8; ++i) {
        int gr = rowBase + row0 + i;
        if (gr >= N) continue;
        float s1 = __ldg(sv + gr), t1 = __ldg(tv + gr);
        float o[8];
        #pragma unroll
        for (int j = 0; j < 4; ++j) {
            float2 v = up2(acc[i][j]);
            o[2 * j] = v.x; o[2 * j + 1] = v.y;
        }
        #pragma unroll
        for (int jj = 0; jj < 8; ++jj) {
            int col = col0 + jj;
            float c = o[jj] + s1 * __ldg(th1 + col * 2) + t1 * __ldg(th1 + col * 2 + 1);
            o[jj] = fmaxf(c, 0.0f);
        }
        float4* dp = reinterpret_cast<float4*>(g_mu + (size_t)gr * 128 + col0);
        dp[0] = make_float4(o[0], o[1], o[2], o[3]);
        dp[1] = make_float4(o[4], o[5], o[6], o[7]);
    }
}

// ---------------------------------------------------------------------------
// Stage C: mu' = [mu ; relu(deg*mu - nb)] @ h_theta^T   (K=256, two chunks)
//          also accumulates column sums into g_summu
// ---------------------------------------------------------------------------
__global__ void __launch_bounds__(256)
mup_kernel(int N) {
    extern __shared__ float sm[];
    float* As = sm;
    float* Bs = sm + 128 * 128;
    int tid = threadIdx.x;
    int lane = tid & 31, w = tid >> 5;
    int rowBase = blockIdx.x * 128;
    int row0 = (tid >> 4) * 8, col0 = (tid & 15) * 8;
    unsigned long long acc[8][4] = {};

    // chunk 0: A = mu
    #pragma unroll
    for (int rb = 0; rb < 4; ++rb) {
        int r = rb * 32 + lane;
        int gr = rowBase + r;
        bool ok = gr < N;
        #pragma unroll
        for (int cc = 0; cc < 4; ++cc) {
            int k4 = w + 8 * cc;
            float4 v = ok ? __ldg(reinterpret_cast<const float4*>(g_mu + (size_t)gr * 128) + k4)
                          : make_float4(0.f, 0.f, 0.f, 0.f);
            int kb = k4 * 4;
            As[(kb + 0) * 128 + r] = v.x;
            As[(kb + 1) * 128 + r] = v.y;
            As[(kb + 2) * 128 + r] = v.z;
            As[(kb + 3) * 128 + r] = v.w;
        }
    }
    load_B(Bs, g_Bh, 0, tid);
    __syncthreads();
    mma128(As, Bs, row0, col0, acc);
    __syncthreads();

    // chunk 1: A = relu(deg*mu - nb)
    #pragma unroll
    for (int rb = 0; rb < 4; ++rb) {
        int r = rb * 32 + lane;
        int gr = rowBase + r;
        bool ok = gr < N;
        float dg = ok ? g_deg[gr] : 0.0f;
        #pragma unroll
        for (int cc = 0; cc < 4; ++cc) {
            int k4 = w + 8 * cc;
            float4 m = ok ? __ldg(reinterpret_cast<const float4*>(g_mu + (size_t)gr * 128) + k4)
                          : make_float4(0.f, 0.f, 0.f, 0.f);
            float4 nb = ok ? __ldg(reinterpret_cast<const float4*>(g_nb + (size_t)gr * 128) + k4)
                           : make_float4(0.f, 0.f, 0.f, 0.f);
            int kb = k4 * 4;
            As[(kb + 0) * 128 + r] = fmaxf(dg * m.x - nb.x, 0.0f);
            As[(kb + 1) * 128 + r] = fmaxf(dg * m.y - nb.y, 0.0f);
            As[(kb + 2) * 128 + r] = fmaxf(dg * m.z - nb.z, 0.0f);
            As[(kb + 3) * 128 + r] = fmaxf(dg * m.w - nb.w, 0.0f);
        }
    }
    load_B(Bs, g_Bh, 128, tid);
    __syncthreads();
    mma128(As, Bs, row0, col0, acc);
    __syncthreads();  // smem free for reduction reuse

    // epilogue: store mu' and reduce column sums
    float colp[8] = {0.f, 0.f, 0.f, 0.f, 0.f, 0.f, 0.f, 0.f};
    #pragma unroll
    for (int i = 0; i < 8; ++i) {
        int gr = rowBase + row0 + i;
        float o[8];
        #pragma unroll
        for (int j = 0; j < 4; ++j) {
            float2 v = up2(acc[i][j]);
            o[2 * j] = v.x; o[2 * j + 1] = v.y;
        }
        #pragma unroll
        for (int jj = 0; jj < 8; ++jj) colp[jj] += o[jj];  // padded rows are 0
        if (gr < N) {
            float4* dp = reinterpret_cast<float4*>(g_mup + (size_t)gr * 128 + col0);
            dp[0] = make_float4(o[0], o[1], o[2], o[3]);
            dp[1] = make_float4(o[4], o[5], o[6], o[7]);
        }
    }
    float* part = sm;  // reuse As region: 16 x 128
    int ty = tid >> 4;
    #pragma unroll
    for (int jj = 0; jj < 8; ++jj) part[ty * 128 + col0 + jj] = colp[jj];
    __syncthreads();
    if (tid < 128) {
        float s = 0.0f;
        #pragma unroll
        for (int t = 0; t < 16; ++t) s += part[t * 128 + tid];
        atomicAdd(&g_summu[tid], s);
    }
}

// ---------------------------------------------------------------------------
// Q head: c_up = sum_p relu((theta4 @ sum_mu')[p]) * theta3[p]   (one block)
// ---------------------------------------------------------------------------
__global__ void qhead_kernel(const float* __restrict__ th4,
                             const float* __restrict__ th3) {
    __shared__ float svv[128];
    __shared__ float rbuf[4];
    int tid = threadIdx.x;
    svv[tid] = g_summu[tid];
    __syncthreads();
    float up = 0.0f;
    #pragma unroll 4
    for (int q = 0; q < 128; ++q) up += th4[tid * 128 + q] * svv[q];
    float v = fmaxf(up, 0.0f) * th3[tid];
    #pragma unroll
    for (int o = 16; o; o >>= 1) v += __shfl_xor_sync(0xFFFFFFFFu, v, o);
    if ((tid & 31) == 0) rbuf[tid >> 5] = v;
    __syncthreads();
    if (tid == 0) g_cup = rbuf[0] + rbuf[1] + rbuf[2] + rbuf[3];
}

// ---------------------------------------------------------------------------
// Stage E: out[v] = c_up + sum_j relu((mu' @ theta5^T)[v,j]) * theta3[128+j]
// ---------------------------------------------------------------------------
__global__ void __launch_bounds__(256)
out_kernel(const float* __restrict__ th3, float* __restrict__ out, int N) {
    extern __shared__ float sm[];
    float* As = sm;
    float* Bs = sm + 128 * 128;
    int tid = threadIdx.x;
    int lane = tid & 31, w = tid >> 5;
    int rowBase = blockIdx.x * 128;

    #pragma unroll
    for (int rb = 0; rb < 4; ++rb) {
        int r = rb * 32 + lane;
        int gr = rowBase + r;
        bool ok = gr < N;
        #pragma unroll
        for (int cc = 0; cc < 4; ++cc) {
            int k4 = w + 8 * cc;
            float4 v = ok ? __ldg(reinterpret_cast<const float4*>(g_mup + (size_t)gr * 128) + k4)
                          : make_float4(0.f, 0.f, 0.f, 0.f);
            int kb = k4 * 4;
            As[(kb + 0) * 128 + r] = v.x;
            As[(kb + 1) * 128 + r] = v.y;
            As[(kb + 2) * 128 + r] = v.z;
            As[(kb + 3) * 128 + r] = v.w;
        }
    }
    load_B(Bs, g_B5, 0, tid);
    __syncthreads();

    unsigned long long acc[8][4] = {};
    int row0 = (tid >> 4) * 8, col0 = (tid & 15) * 8;
    mma128(As, Bs, row0, col0, acc);
    __syncthreads();  // smem free for reduction reuse

    // per-thread weighted relu row partials
    float rowp[8];
    #pragma unroll
    for (int i = 0; i < 8; ++i) {
        float rp = 0.0f;
        #pragma unroll
        for (int j = 0; j < 4; ++j) {
            float2 v = up2(acc[i][j]);
            rp += fmaxf(v.x, 0.0f) * __ldg(th3 + 128 + col0 + 2 * j);
            rp += fmaxf(v.y, 0.0f) * __ldg(th3 + 128 + col0 + 2 * j + 1);
        }
        rowp[i] = rp;
    }
    float* red = sm;  // 16 x 129 (conflict-free stride)
    int tx = tid & 15;
    #pragma unroll
    for (int i = 0; i < 8; ++i) red[tx * 129 + row0 + i] = rowp[i];
    __syncthreads();
    if (tid < 128) {
        float s = 0.0f;
        #pragma unroll
        for (int t = 0; t < 16; ++t) s += red[t * 129 + tid];
        int gr = rowBase + tid;
        if (gr < N) out[gr] = g_cup + s;
    }
}

// ---------------------------------------------------------------------------
// Launch
// ---------------------------------------------------------------------------
extern "C" void kernel_launch(void* const* d_in, const int* in_sizes, int n_in,
                              void* d_out, int out_size) {
    const float* s_v  = (const float*)d_in[0];
    const float* t_v  = (const float*)d_in[1];
    const float* x    = (const float*)d_in[2];
    const int*   esrc = (const int*)  d_in[3];
    const int*   edst = (const int*)  d_in[4];
    const float* th1  = (const float*)d_in[5];
    const float* th2  = (const float*)d_in[6];
    const float* th3  = (const float*)d_in[7];
    const float* th4  = (const float*)d_in[8];
    const float* th5  = (const float*)d_in[9];
    const float* hth  = (const float*)d_in[10];
    float* out = (float*)d_out;

    int N = in_sizes[0];
    int E = in_sizes[3];
    int tiles = (N + 127) / 128;
    int smem = 2 * 128 * 128 * (int)sizeof(float);  // 128 KB

    cudaFuncSetAttribute(mu_kernel,  cudaFuncAttributeMaxDynamicSharedMemorySize, smem);
    cudaFuncSetAttribute(mup_kernel, cudaFuncAttributeMaxDynamicSharedMemorySize, smem);
    cudaFuncSetAttribute(out_kernel, cudaFuncAttributeMaxDynamicSharedMemorySize, smem);

    prep_kernel<<<64, 256>>>(th2, th5, hth);
    zero_kernel<<<4096, 256>>>(N);
    norm_kernel<<<(N + 7) / 8, 256>>>(x, N);
    mu_kernel<<<tiles, 256, smem>>>(x, s_v, t_v, th1, N);
    edge_kernel<<<8192, 256>>>(esrc, edst, E);
    mup_kernel<<<tiles, 256, smem>>>(N);
    qhead_kernel<<<1, 128>>>(th4, th3);
    out_kernel<<<tiles, 256, smem>>>(th3, out, N);
}

// round 10
// speedup vs baseline: 1.2560x; 1.2000x over previous
#include <cuda_runtime.h>
#include <cstdint>

// ---------------------------------------------------------------------------
// Problem constants (shapes fixed by the dataset; N,E taken from in_sizes)
// ---------------------------------------------------------------------------
#define NMAX 100000
#define PDIM 128

// Scratch (device globals: allocation-free per harness rules)
__device__ float g_mu  [NMAX * PDIM];   // mu  [N,128]
__device__ float g_nb  [NMAX * PDIM];   // nb_sum [N,128] (atomics)
__device__ float g_mup [NMAX * PDIM];   // mu' [N,128]
__device__ float g_deg [NMAX];
__device__ float g_inv [NMAX];          // 1/||x_v||
__device__ float g_summu[PDIM];
__device__ float g_B2 [128 * 128];      // theta2^T  (Bt[k][p])
__device__ float g_B5 [128 * 128];      // theta5^T
__device__ float g_Bh [256 * 128];      // h_theta^T
__device__ float g_cup;                 // scalar shared "up" contribution

// ---------------------------------------------------------------------------
// f32x2 packed-FMA helpers (Blackwell packed fp32 path: 2x FFMA throughput)
// ---------------------------------------------------------------------------
__device__ __forceinline__ unsigned long long pk2(float x, float y) {
    unsigned long long r;
    asm("mov.b64 %0, {%1, %2};" : "=l"(r) : "f"(x), "f"(y));
    return r;
}
__device__ __forceinline__ void fma2(unsigned long long& c,
                                     unsigned long long a,
                                     unsigned long long b) {
    asm("fma.rn.f32x2 %0, %1, %2, %0;" : "+l"(c) : "l"(a), "l"(b));
}
__device__ __forceinline__ float2 up2(unsigned long long v) {
    float2 r;
    asm("mov.b64 {%0, %1}, %2;" : "=f"(r.x), "=f"(r.y) : "l"(v));
    return r;
}

// ---------------------------------------------------------------------------
// prep: transpose the small weight matrices once per call; zero sum_mu'
// ---------------------------------------------------------------------------
__global__ void prep_kernel(const float* __restrict__ th2,
                            const float* __restrict__ th5,
                            const float* __restrict__ hth) {
    int idx = blockIdx.x * blockDim.x + threadIdx.x;
    int stride = gridDim.x * blockDim.x;
    for (int i = idx; i < 128 * 128; i += stride) {
        int k = i >> 7, p = i & 127;
        g_B2[i] = th2[p * 128 + k];
        g_B5[i] = th5[p * 128 + k];
    }
    for (int i = idx; i < 256 * 128; i += stride) {
        int k = i >> 7, p = i & 127;
        g_Bh[i] = hth[p * 256 + k];
    }
    if (idx < PDIM) g_summu[idx] = 0.0f;
}

// zero nb_sum and deg
__global__ void zero_kernel(int N) {
    int idx = blockIdx.x * blockDim.x + threadIdx.x;
    int stride = gridDim.x * blockDim.x;
    int n4 = N * 32;  // N*128 floats as float4
    float4 z = make_float4(0.f, 0.f, 0.f, 0.f);
    float4* nb4 = reinterpret_cast<float4*>(g_nb);
    for (int i = idx; i < n4; i += stride) nb4[i] = z;
    for (int i = idx; i < N; i += stride) g_deg[i] = 0.0f;
}

// per-node inverse row norm of x (one warp per node)
__global__ void norm_kernel(const float* __restrict__ x, int N) {
    int warp = (blockIdx.x * blockDim.x + threadIdx.x) >> 5;
    int lane = threadIdx.x & 31;
    if (warp >= N) return;
    float4 v = reinterpret_cast<const float4*>(x + (size_t)warp * 128)[lane];
    float s = v.x * v.x + v.y * v.y + v.z * v.z + v.w * v.w;
    #pragma unroll
    for (int o = 16; o; o >>= 1) s += __shfl_xor_sync(0xFFFFFFFFu, s, o);
    if (lane == 0) g_inv[warp] = (s > 0.0f) ? rsqrtf(s) : 1.0f;
}

// ---------------------------------------------------------------------------
// Edge aggregation: nb_sum[src] += mu[dst]; deg[src] += 1   (warp per edge)
// 2-way unrolled so both gathers are in flight before the reds (the asm
// memory clobber otherwise serializes iterations).
// ---------------------------------------------------------------------------
__device__ __forceinline__ void edge_red(int s, float4 v, int lane) {
    float* p = g_nb + (size_t)s * 128 + lane * 4;
    asm volatile("red.global.add.v4.f32 [%0], {%1, %2, %3, %4};"
                 :: "l"(p), "f"(v.x), "f"(v.y), "f"(v.z), "f"(v.w)
                 : "memory");
}

__global__ void edge_kernel(const int* __restrict__ src,
                            const int* __restrict__ dst, int E) {
    int lane = threadIdx.x & 31;
    int warp = (blockIdx.x * blockDim.x + threadIdx.x) >> 5;
    int nwarps = (gridDim.x * blockDim.x) >> 5;
    for (int e = warp; e < E; e += 2 * nwarps) {
        int e2 = e + nwarps;
        int s0 = __ldg(src + e);
        int d0 = __ldg(dst + e);
        int s1 = 0, d1 = 0;
        bool ok2 = e2 < E;
        if (ok2) { s1 = __ldg(src + e2); d1 = __ldg(dst + e2); }
        float4 v0 = __ldg(reinterpret_cast<const float4*>(g_mu + (size_t)d0 * 128) + lane);
        float4 v1 = make_float4(0.f, 0.f, 0.f, 0.f);
        if (ok2) v1 = __ldg(reinterpret_cast<const float4*>(g_mu + (size_t)d1 * 128) + lane);
        edge_red(s0, v0, lane);
        if (ok2) edge_red(s1, v1, lane);
        if (lane == 0) {
            atomicAdd(g_deg + s0, 1.0f);
            if (ok2) atomicAdd(g_deg + s1, 1.0f);
        }
    }
}

// ---------------------------------------------------------------------------
// GEMM core: 128x128 tile, 256 threads, split 4+4 per-thread tile for
// conflict-free LDS. Thread owns rows {r4..r4+3, r4+64..+67} x cols
// {c4..c4+3, c4+64..+67}; r4=(tid>>4)*4 (half-warp broadcast A reads),
// c4=(tid&15)*4 (each 8-lane quarter reads 128 contiguous B bytes).
// K is processed in 64-deep smem chunks so smem <= 96 KB -> 2 CTAs/SM.
// ---------------------------------------------------------------------------
__device__ __forceinline__ void mma64(const float* __restrict__ As,
                                      const float* __restrict__ Bs,
                                      int r4, int c4,
                                      unsigned long long (&acc)[8][4]) {
    #pragma unroll 4
    for (int k = 0; k < 64; ++k) {
        float4 a0 = *reinterpret_cast<const float4*>(As + k * 128 + r4);
        float4 a1 = *reinterpret_cast<const float4*>(As + k * 128 + r4 + 64);
        float4 b0 = *reinterpret_cast<const float4*>(Bs + k * 128 + c4);
        float4 b1 = *reinterpret_cast<const float4*>(Bs + k * 128 + c4 + 64);
        unsigned long long bp[4] = { pk2(b0.x, b0.y), pk2(b0.z, b0.w),
                                     pk2(b1.x, b1.y), pk2(b1.z, b1.w) };
        float av[8] = { a0.x, a0.y, a0.z, a0.w, a1.x, a1.y, a1.z, a1.w };
        #pragma unroll
        for (int i = 0; i < 8; ++i) {
            unsigned long long ap = pk2(av[i], av[i]);
            #pragma unroll
            for (int j = 0; j < 4; ++j) fma2(acc[i][j], ap, bp[j]);
        }
    }
}

// full 128-k B tile (64 KB): 16 float4 per thread
__device__ __forceinline__ void load_B128(float* Bs, const float* __restrict__ Bt,
                                          int tid) {
    const float4* srcp = reinterpret_cast<const float4*>(Bt);
    float4* dstp = reinterpret_cast<float4*>(Bs);
    #pragma unroll
    for (int r = 0; r < 16; ++r) dstp[tid + 256 * r] = srcp[tid + 256 * r];
}

// 64-k B chunk (32 KB): 8 float4 per thread
__device__ __forceinline__ void load_B64(float* Bs, const float* __restrict__ Bt,
                                         int tid) {
    const float4* srcp = reinterpret_cast<const float4*>(Bt);
    float4* dstp = reinterpret_cast<float4*>(Bs);
    #pragma unroll
    for (int r = 0; r < 8; ++r) dstp[tid + 256 * r] = srcp[tid + 256 * r];
}

// load a 64-k half of a plain [N,128] matrix, transposed As[k][row]
__device__ __forceinline__ void loadA_plain(float* As, const float* __restrict__ src,
                                            int rowBase, int N, int h,
                                            int lane, int w) {
    #pragma unroll
    for (int rb = 0; rb < 4; ++rb) {
        int r = rb * 32 + lane;
        int gr = rowBase + r;
        bool ok = gr < N;
        #pragma unroll
        for (int cc = 0; cc < 2; ++cc) {
            int k4 = w + 8 * cc;   // 0..15 within half
            float4 v = ok ? __ldg(reinterpret_cast<const float4*>(src + (size_t)gr * 128) + 16 * h + k4)
                          : make_float4(0.f, 0.f, 0.f, 0.f);
            int kb = k4 * 4;
            As[(kb + 0) * 128 + r] = v.x;
            As[(kb + 1) * 128 + r] = v.y;
            As[(kb + 2) * 128 + r] = v.z;
            As[(kb + 3) * 128 + r] = v.w;
        }
    }
}

// ---------------------------------------------------------------------------
// Stage A: mu = relu(xn @ theta2^T + conn @ theta1^T)
// smem: As 32 KB (64-k chunk) + Bs 64 KB (full K) = 96 KB -> 2 CTAs/SM
// ---------------------------------------------------------------------------
__global__ void __launch_bounds__(256, 2)
mu_kernel(const float* __restrict__ x, const float* __restrict__ sv,
          const float* __restrict__ tv, const float* __restrict__ th1, int N) {
    extern __shared__ float sm[];
    float* As = sm;                 // 64*128
    float* Bs = sm + 64 * 128;      // 128*128
    int tid = threadIdx.x;
    int lane = tid & 31, w = tid >> 5;
    int rowBase = blockIdx.x * 128;
    int r4 = (tid >> 4) * 4, c4 = (tid & 15) * 4;
    unsigned long long acc[8][4] = {};

    load_B128(Bs, g_B2, tid);
    // A half 0 with inv-norm scaling
    #pragma unroll
    for (int rb = 0; rb < 4; ++rb) {
        int r = rb * 32 + lane;
        int gr = rowBase + r;
        bool ok = gr < N;
        float sc = ok ? g_inv[gr] : 0.0f;
        #pragma unroll
        for (int cc = 0; cc < 2; ++cc) {
            int k4 = w + 8 * cc;
            float4 v = ok ? __ldg(reinterpret_cast<const float4*>(x + (size_t)gr * 128) + k4)
                          : make_float4(0.f, 0.f, 0.f, 0.f);
            int kb = k4 * 4;
            As[(kb + 0) * 128 + r] = v.x * sc;
            As[(kb + 1) * 128 + r] = v.y * sc;
            As[(kb + 2) * 128 + r] = v.z * sc;
            As[(kb + 3) * 128 + r] = v.w * sc;
        }
    }
    __syncthreads();
    mma64(As, Bs, r4, c4, acc);
    __syncthreads();
    // A half 1
    #pragma unroll
    for (int rb = 0; rb < 4; ++rb) {
        int r = rb * 32 + lane;
        int gr = rowBase + r;
        bool ok = gr < N;
        float sc = ok ? g_inv[gr] : 0.0f;
        #pragma unroll
        for (int cc = 0; cc < 2; ++cc) {
            int k4 = w + 8 * cc;
            float4 v = ok ? __ldg(reinterpret_cast<const float4*>(x + (size_t)gr * 128) + 16 + k4)
                          : make_float4(0.f, 0.f, 0.f, 0.f);
            int kb = k4 * 4;
            As[(kb + 0) * 128 + r] = v.x * sc;
            As[(kb + 1) * 128 + r] = v.y * sc;
            As[(kb + 2) * 128 + r] = v.z * sc;
            As[(kb + 3) * 128 + r] = v.w * sc;
        }
    }
    __syncthreads();
    mma64(As, Bs + 64 * 128, r4, c4, acc);

    // epilogue: + conn term, relu, store
    #pragma unroll
    for (int i = 0; i < 8; ++i) {
        int gr = rowBase + r4 + ((i < 4) ? i : (60 + i));
        if (gr >= N) continue;
        float s1 = __ldg(sv + gr), t1 = __ldg(tv + gr);
        float o[8];
        #pragma unroll
        for (int j = 0; j < 4; ++j) {
            float2 v = up2(acc[i][j]);
            o[2 * j] = v.x; o[2 * j + 1] = v.y;
        }
        #pragma unroll
        for (int jj = 0; jj < 8; ++jj) {
            int col = (jj < 4) ? (c4 + jj) : (c4 + 60 + jj);
            float c = o[jj] + s1 * __ldg(th1 + col * 2) + t1 * __ldg(th1 + col * 2 + 1);
            o[jj] = fmaxf(c, 0.0f);
        }
        *reinterpret_cast<float4*>(g_mu + (size_t)gr * 128 + c4) =
            make_float4(o[0], o[1], o[2], o[3]);
        *reinterpret_cast<float4*>(g_mu + (size_t)gr * 128 + c4 + 64) =
            make_float4(o[4], o[5], o[6], o[7]);
    }
}

// ---------------------------------------------------------------------------
// Stage C: mu' = [mu ; relu(deg*mu - nb)] @ h_theta^T   (K=256, 4 stages)
// smem: As 32 KB + Bs 32 KB = 64 KB
// ---------------------------------------------------------------------------
__global__ void __launch_bounds__(256, 2)
mup_kernel(int N) {
    extern __shared__ float sm[];
    float* As = sm;                 // 64*128
    float* Bs = sm + 64 * 128;      // 64*128
    int tid = threadIdx.x;
    int lane = tid & 31, w = tid >> 5;
    int rowBase = blockIdx.x * 128;
    int r4 = (tid >> 4) * 4, c4 = (tid & 15) * 4;
    unsigned long long acc[8][4] = {};

    #pragma unroll
    for (int s = 0; s < 4; ++s) {
        if (s) __syncthreads();
        if (s < 2) {
            loadA_plain(As, g_mu, rowBase, N, s, lane, w);
        } else {
            int h = s - 2;
            #pragma unroll
            for (int rb = 0; rb < 4; ++rb) {
                int r = rb * 32 + lane;
                int gr = rowBase + r;
                bool ok = gr < N;
                float dg = ok ? g_deg[gr] : 0.0f;
                #pragma unroll
                for (int cc = 0; cc < 2; ++cc) {
                    int k4 = w + 8 * cc;
                    float4 m = ok ? __ldg(reinterpret_cast<const float4*>(g_mu + (size_t)gr * 128) + 16 * h + k4)
                                  : make_float4(0.f, 0.f, 0.f, 0.f);
                    float4 nb = ok ? __ldg(reinterpret_cast<const float4*>(g_nb + (size_t)gr * 128) + 16 * h + k4)
                                   : make_float4(0.f, 0.f, 0.f, 0.f);
                    int kb = k4 * 4;
                    As[(kb + 0) * 128 + r] = fmaxf(dg * m.x - nb.x, 0.0f);
                    As[(kb + 1) * 128 + r] = fmaxf(dg * m.y - nb.y, 0.0f);
                    As[(kb + 2) * 128 + r] = fmaxf(dg * m.z - nb.z, 0.0f);
                    As[(kb + 3) * 128 + r] = fmaxf(dg * m.w - nb.w, 0.0f);
                }
            }
        }
        load_B64(Bs, g_Bh + (size_t)s * 64 * 128, tid);
        __syncthreads();
        mma64(As, Bs, r4, c4, acc);
    }
    __syncthreads();  // smem free for reduction reuse

    // epilogue: store mu' and reduce column sums
    float colp[8] = {0.f, 0.f, 0.f, 0.f, 0.f, 0.f, 0.f, 0.f};
    #pragma unroll
    for (int i = 0; i < 8; ++i) {
        int gr = rowBase + r4 + ((i < 4) ? i : (60 + i));
        float o[8];
        #pragma unroll
        for (int j = 0; j < 4; ++j) {
            float2 v = up2(acc[i][j]);
            o[2 * j] = v.x; o[2 * j + 1] = v.y;
        }
        #pragma unroll
        for (int jj = 0; jj < 8; ++jj) colp[jj] += o[jj];  // padded rows are 0
        if (gr < N) {
            *reinterpret_cast<float4*>(g_mup + (size_t)gr * 128 + c4) =
                make_float4(o[0], o[1], o[2], o[3]);
            *reinterpret_cast<float4*>(g_mup + (size_t)gr * 128 + c4 + 64) =
                make_float4(o[4], o[5], o[6], o[7]);
        }
    }
    float* part = sm;  // reuse: 16 x 128
    int ty = tid >> 4;
    #pragma unroll
    for (int jj = 0; jj < 8; ++jj) {
        int col = (jj < 4) ? (c4 + jj) : (c4 + 60 + jj);
        part[ty * 128 + col] = colp[jj];
    }
    __syncthreads();
    if (tid < 128) {
        float s = 0.0f;
        #pragma unroll
        for (int t = 0; t < 16; ++t) s += part[t * 128 + tid];
        atomicAdd(&g_summu[tid], s);
    }
}

// ---------------------------------------------------------------------------
// Q head: c_up = sum_p relu((theta4 @ sum_mu')[p]) * theta3[p]   (one block)
// ---------------------------------------------------------------------------
__global__ void qhead_kernel(const float* __restrict__ th4,
                             const float* __restrict__ th3) {
    __shared__ float svv[128];
    __shared__ float rbuf[4];
    int tid = threadIdx.x;
    svv[tid] = g_summu[tid];
    __syncthreads();
    float up = 0.0f;
    #pragma unroll 4
    for (int q = 0; q < 128; ++q) up += th4[tid * 128 + q] * svv[q];
    float v = fmaxf(up, 0.0f) * th3[tid];
    #pragma unroll
    for (int o = 16; o; o >>= 1) v += __shfl_xor_sync(0xFFFFFFFFu, v, o);
    if ((tid & 31) == 0) rbuf[tid >> 5] = v;
    __syncthreads();
    if (tid == 0) g_cup = rbuf[0] + rbuf[1] + rbuf[2] + rbuf[3];
}

// ---------------------------------------------------------------------------
// Stage E: out[v] = c_up + sum_j relu((mu' @ theta5^T)[v,j]) * theta3[128+j]
// smem: As 32 KB + Bs 64 KB = 96 KB
// ---------------------------------------------------------------------------
__global__ void __launch_bounds__(256, 2)
out_kernel(const float* __restrict__ th3, float* __restrict__ out, int N) {
    extern __shared__ float sm[];
    float* As = sm;
    float* Bs = sm + 64 * 128;
    int tid = threadIdx.x;
    int lane = tid & 31, w = tid >> 5;
    int rowBase = blockIdx.x * 128;
    int r4 = (tid >> 4) * 4, c4 = (tid & 15) * 4;
    unsigned long long acc[8][4] = {};

    load_B128(Bs, g_B5, tid);
    loadA_plain(As, g_mup, rowBase, N, 0, lane, w);
    __syncthreads();
    mma64(As, Bs, r4, c4, acc);
    __syncthreads();
    loadA_plain(As, g_mup, rowBase, N, 1, lane, w);
    __syncthreads();
    mma64(As, Bs + 64 * 128, r4, c4, acc);
    __syncthreads();  // smem free for reduction reuse

    // per-thread weighted relu row partials
    float rowp[8];
    #pragma unroll
    for (int i = 0; i < 8; ++i) {
        float rp = 0.0f;
        #pragma unroll
        for (int j = 0; j < 4; ++j) {
            float2 v = up2(acc[i][j]);
            int cbase = (j < 2) ? (c4 + 2 * j) : (c4 + 64 + 2 * (j - 2));
            rp += fmaxf(v.x, 0.0f) * __ldg(th3 + 128 + cbase);
            rp += fmaxf(v.y, 0.0f) * __ldg(th3 + 128 + cbase + 1);
        }
        rowp[i] = rp;
    }
    float* red = sm;  // 16 x 129 (conflict-free stride)
    int tx = tid & 15;
    #pragma unroll
    for (int i = 0; i < 8; ++i) {
        int row = r4 + ((i < 4) ? i : (60 + i));
        red[tx * 129 + row] = rowp[i];
    }
    __syncthreads();
    if (tid < 128) {
        float s = 0.0f;
        #pragma unroll
        for (int t = 0; t < 16; ++t) s += red[t * 129 + tid];
        int gr = rowBase + tid;
        if (gr < N) out[gr] = g_cup + s;
    }
}

// ---------------------------------------------------------------------------
// Launch
// ---------------------------------------------------------------------------
extern "C" void kernel_launch(void* const* d_in, const int* in_sizes, int n_in,
                              void* d_out, int out_size) {
    const float* s_v  = (const float*)d_in[0];
    const float* t_v  = (const float*)d_in[1];
    const float* x    = (const float*)d_in[2];
    const int*   esrc = (const int*)  d_in[3];
    const int*   edst = (const int*)  d_in[4];
    const float* th1  = (const float*)d_in[5];
    const float* th2  = (const float*)d_in[6];
    const float* th3  = (const float*)d_in[7];
    const float* th4  = (const float*)d_in[8];
    const float* th5  = (const float*)d_in[9];
    const float* hth  = (const float*)d_in[10];
    float* out = (float*)d_out;

    int N = in_sizes[0];
    int E = in_sizes[3];
    int tiles = (N + 127) / 128;
    int smem96 = (64 * 128 + 128 * 128) * (int)sizeof(float);  // 96 KB
    int smem64 = (64 * 128 + 64 * 128) * (int)sizeof(float);   // 64 KB

    cudaFuncSetAttribute(mu_kernel,  cudaFuncAttributeMaxDynamicSharedMemorySize, smem96);
    cudaFuncSetAttribute(mup_kernel, cudaFuncAttributeMaxDynamicSharedMemorySize, smem64);
    cudaFuncSetAttribute(out_kernel, cudaFuncAttributeMaxDynamicSharedMemorySize, smem96);

    prep_kernel<<<64, 256>>>(th2, th5, hth);
    zero_kernel<<<4096, 256>>>(N);
    norm_kernel<<<(N + 7) / 8, 256>>>(x, N);
    mu_kernel<<<tiles, 256, smem96>>>(x, s_v, t_v, th1, N);
    edge_kernel<<<8192, 256>>>(esrc, edst, E);
    mup_kernel<<<tiles, 256, smem64>>>(N);
    qhead_kernel<<<1, 128>>>(th4, th3);
    out_kernel<<<tiles, 256, smem96>>>(th3, out, N);
}

// round 11
// speedup vs baseline: 1.2568x; 1.0006x over previous
#include <cuda_runtime.h>
#include <cstdint>

// ---------------------------------------------------------------------------
// Problem constants (shapes fixed by the dataset; N,E taken from in_sizes)
// ---------------------------------------------------------------------------
#define NMAX 100000
#define PDIM 128

// Scratch (device globals: allocation-free per harness rules)
__device__ float g_mu  [NMAX * PDIM];   // mu  [N,128]
__device__ float g_nb  [NMAX * PDIM];   // nb_sum [N,128] (atomics)
__device__ float g_mup [NMAX * PDIM];   // mu' [N,128]
__device__ float g_deg [NMAX];
__device__ float g_inv [NMAX];          // 1/||x_v||
__device__ float g_summu[PDIM];
__device__ float g_B2 [128 * 128];      // theta2^T  (Bt[k][p])
__device__ float g_B5 [128 * 128];      // theta5^T
__device__ float g_Bh [256 * 128];      // h_theta^T
__device__ float g_cup;                 // scalar shared "up" contribution

// ---------------------------------------------------------------------------
// f32x2 packed-FMA helpers (Blackwell packed fp32 path: 2x FFMA throughput)
// ---------------------------------------------------------------------------
__device__ __forceinline__ unsigned long long pk2(float x, float y) {
    unsigned long long r;
    asm("mov.b64 %0, {%1, %2};" : "=l"(r) : "f"(x), "f"(y));
    return r;
}
__device__ __forceinline__ void fma2(unsigned long long& c,
                                     unsigned long long a,
                                     unsigned long long b) {
    asm("fma.rn.f32x2 %0, %1, %2, %0;" : "+l"(c) : "l"(a), "l"(b));
}
__device__ __forceinline__ float2 up2(unsigned long long v) {
    float2 r;
    asm("mov.b64 {%0, %1}, %2;" : "=f"(r.x), "=f"(r.y) : "l"(v));
    return r;
}

// ---------------------------------------------------------------------------
// prep: transpose the small weight matrices once per call; zero sum_mu'
// ---------------------------------------------------------------------------
__global__ void prep_kernel(const float* __restrict__ th2,
                            const float* __restrict__ th5,
                            const float* __restrict__ hth) {
    int idx = blockIdx.x * blockDim.x + threadIdx.x;
    int stride = gridDim.x * blockDim.x;
    for (int i = idx; i < 128 * 128; i += stride) {
        int k = i >> 7, p = i & 127;
        g_B2[i] = th2[p * 128 + k];
        g_B5[i] = th5[p * 128 + k];
    }
    for (int i = idx; i < 256 * 128; i += stride) {
        int k = i >> 7, p = i & 127;
        g_Bh[i] = hth[p * 256 + k];
    }
    if (idx < PDIM) g_summu[idx] = 0.0f;
}

// zero nb_sum and deg
__global__ void zero_kernel(int N) {
    int idx = blockIdx.x * blockDim.x + threadIdx.x;
    int stride = gridDim.x * blockDim.x;
    int n4 = N * 32;  // N*128 floats as float4
    float4 z = make_float4(0.f, 0.f, 0.f, 0.f);
    float4* nb4 = reinterpret_cast<float4*>(g_nb);
    for (int i = idx; i < n4; i += stride) nb4[i] = z;
    for (int i = idx; i < N; i += stride) g_deg[i] = 0.0f;
}

// per-node inverse row norm of x (one warp per node)
__global__ void norm_kernel(const float* __restrict__ x, int N) {
    int warp = (blockIdx.x * blockDim.x + threadIdx.x) >> 5;
    int lane = threadIdx.x & 31;
    if (warp >= N) return;
    float4 v = reinterpret_cast<const float4*>(x + (size_t)warp * 128)[lane];
    float s = v.x * v.x + v.y * v.y + v.z * v.z + v.w * v.w;
    #pragma unroll
    for (int o = 16; o; o >>= 1) s += __shfl_xor_sync(0xFFFFFFFFu, s, o);
    if (lane == 0) g_inv[warp] = (s > 0.0f) ? rsqrtf(s) : 1.0f;
}

// ---------------------------------------------------------------------------
// Edge aggregation: nb_sum[src] += mu[dst]; deg[src] += 1   (warp per edge)
// 2-way unrolled so both gathers are in flight before the reds (the asm
// memory clobber otherwise serializes iterations).
// ---------------------------------------------------------------------------
__device__ __forceinline__ void edge_red(int s, float4 v, int lane) {
    float* p = g_nb + (size_t)s * 128 + lane * 4;
    asm volatile("red.global.add.v4.f32 [%0], {%1, %2, %3, %4};"
                 :: "l"(p), "f"(v.x), "f"(v.y), "f"(v.z), "f"(v.w)
                 : "memory");
}

__global__ void edge_kernel(const int* __restrict__ src,
                            const int* __restrict__ dst, int E) {
    int lane = threadIdx.x & 31;
    int warp = (blockIdx.x * blockDim.x + threadIdx.x) >> 5;
    int nwarps = (gridDim.x * blockDim.x) >> 5;
    for (int e = warp; e < E; e += 2 * nwarps) {
        int e2 = e + nwarps;
        int s0 = __ldg(src + e);
        int d0 = __ldg(dst + e);
        int s1 = 0, d1 = 0;
        bool ok2 = e2 < E;
        if (ok2) { s1 = __ldg(src + e2); d1 = __ldg(dst + e2); }
        float4 v0 = __ldg(reinterpret_cast<const float4*>(g_mu + (size_t)d0 * 128) + lane);
        float4 v1 = make_float4(0.f, 0.f, 0.f, 0.f);
        if (ok2) v1 = __ldg(reinterpret_cast<const float4*>(g_mu + (size_t)d1 * 128) + lane);
        edge_red(s0, v0, lane);
        if (ok2) edge_red(s1, v1, lane);
        if (lane == 0) {
            atomicAdd(g_deg + s0, 1.0f);
            if (ok2) atomicAdd(g_deg + s1, 1.0f);
        }
    }
}

// ---------------------------------------------------------------------------
// GEMM core: 128x128 tile, 256 threads, split 4+4 per-thread tile for
// conflict-free LDS. Thread owns rows {r4..r4+3, r4+64..+67} x cols
// {c4..c4+3, c4+64..+67}; r4=(tid>>4)*4 (half-warp broadcast A reads),
// c4=(tid&15)*4 (each 8-lane quarter reads 128 contiguous B bytes).
// K is processed in 64-deep smem chunks so smem <= 96 KB -> 2 CTAs/SM.
// ---------------------------------------------------------------------------
__device__ __forceinline__ void mma64(const float* __restrict__ As,
                                      const float* __restrict__ Bs,
                                      int r4, int c4,
                                      unsigned long long (&acc)[8][4]) {
    #pragma unroll 4
    for (int k = 0; k < 64; ++k) {
        float4 a0 = *reinterpret_cast<const float4*>(As + k * 128 + r4);
        float4 a1 = *reinterpret_cast<const float4*>(As + k * 128 + r4 + 64);
        float4 b0 = *reinterpret_cast<const float4*>(Bs + k * 128 + c4);
        float4 b1 = *reinterpret_cast<const float4*>(Bs + k * 128 + c4 + 64);
        unsigned long long bp[4] = { pk2(b0.x, b0.y), pk2(b0.z, b0.w),
                                     pk2(b1.x, b1.y), pk2(b1.z, b1.w) };
        float av[8] = { a0.x, a0.y, a0.z, a0.w, a1.x, a1.y, a1.z, a1.w };
        #pragma unroll
        for (int i = 0; i < 8; ++i) {
            unsigned long long ap = pk2(av[i], av[i]);
            #pragma unroll
            for (int j = 0; j < 4; ++j) fma2(acc[i][j], ap, bp[j]);
        }
    }
}

// full 128-k B tile (64 KB): 16 float4 per thread
__device__ __forceinline__ void load_B128(float* Bs, const float* __restrict__ Bt,
                                          int tid) {
    const float4* srcp = reinterpret_cast<const float4*>(Bt);
    float4* dstp = reinterpret_cast<float4*>(Bs);
    #pragma unroll
    for (int r = 0; r < 16; ++r) dstp[tid + 256 * r] = srcp[tid + 256 * r];
}

// 64-k B chunk (32 KB): 8 float4 per thread
__device__ __forceinline__ void load_B64(float* Bs, const float* __restrict__ Bt,
                                         int tid) {
    const float4* srcp = reinterpret_cast<const float4*>(Bt);
    float4* dstp = reinterpret_cast<float4*>(Bs);
    #pragma unroll
    for (int r = 0; r < 8; ++r) dstp[tid + 256 * r] = srcp[tid + 256 * r];
}

// load a 64-k half of a plain [N,128] matrix, transposed As[k][row]
__device__ __forceinline__ void loadA_plain(float* As, const float* __restrict__ src,
                                            int rowBase, int N, int h,
                                            int lane, int w) {
    #pragma unroll
    for (int rb = 0; rb < 4; ++rb) {
        int r = rb * 32 + lane;
        int gr = rowBase + r;
        bool ok = gr < N;
        #pragma unroll
        for (int cc = 0; cc < 2; ++cc) {
            int k4 = w + 8 * cc;   // 0..15 within half
            float4 v = ok ? __ldg(reinterpret_cast<const float4*>(src + (size_t)gr * 128) + 16 * h + k4)
                          : make_float4(0.f, 0.f, 0.f, 0.f);
            int kb = k4 * 4;
            As[(kb + 0) * 128 + r] = v.x;
            As[(kb + 1) * 128 + r] = v.y;
            As[(kb + 2) * 128 + r] = v.z;
            As[(kb + 3) * 128 + r] = v.w;
        }
    }
}

// ---------------------------------------------------------------------------
// Stage A: mu = relu(xn @ theta2^T + conn @ theta1^T)
// smem: As 32 KB (64-k chunk) + Bs 64 KB (full K) = 96 KB -> 2 CTAs/SM
// ---------------------------------------------------------------------------
__global__ void __launch_bounds__(256, 2)
mu_kernel(const float* __restrict__ x, const float* __restrict__ sv,
          const float* __restrict__ tv, const float* __restrict__ th1, int N) {
    extern __shared__ float sm[];
    float* As = sm;                 // 64*128
    float* Bs = sm + 64 * 128;      // 128*128
    int tid = threadIdx.x;
    int lane = tid & 31, w = tid >> 5;
    int rowBase = blockIdx.x * 128;
    int r4 = (tid >> 4) * 4, c4 = (tid & 15) * 4;
    unsigned long long acc[8][4] = {};

    load_B128(Bs, g_B2, tid);
    // A half 0 with inv-norm scaling
    #pragma unroll
    for (int rb = 0; rb < 4; ++rb) {
        int r = rb * 32 + lane;
        int gr = rowBase + r;
        bool ok = gr < N;
        float sc = ok ? g_inv[gr] : 0.0f;
        #pragma unroll
        for (int cc = 0; cc < 2; ++cc) {
            int k4 = w + 8 * cc;
            float4 v = ok ? __ldg(reinterpret_cast<const float4*>(x + (size_t)gr * 128) + k4)
                          : make_float4(0.f, 0.f, 0.f, 0.f);
            int kb = k4 * 4;
            As[(kb + 0) * 128 + r] = v.x * sc;
            As[(kb + 1) * 128 + r] = v.y * sc;
            As[(kb + 2) * 128 + r] = v.z * sc;
            As[(kb + 3) * 128 + r] = v.w * sc;
        }
    }
    __syncthreads();
    mma64(As, Bs, r4, c4, acc);
    __syncthreads();
    // A half 1
    #pragma unroll
    for (int rb = 0; rb < 4; ++rb) {
        int r = rb * 32 + lane;
        int gr = rowBase + r;
        bool ok = gr < N;
        float sc = ok ? g_inv[gr] : 0.0f;
        #pragma unroll
        for (int cc = 0; cc < 2; ++cc) {
            int k4 = w + 8 * cc;
            float4 v = ok ? __ldg(reinterpret_cast<const float4*>(x + (size_t)gr * 128) + 16 + k4)
                          : make_float4(0.f, 0.f, 0.f, 0.f);
            int kb = k4 * 4;
            As[(kb + 0) * 128 + r] = v.x * sc;
            As[(kb + 1) * 128 + r] = v.y * sc;
            As[(kb + 2) * 128 + r] = v.z * sc;
            As[(kb + 3) * 128 + r] = v.w * sc;
        }
    }
    __syncthreads();
    mma64(As, Bs + 64 * 128, r4, c4, acc);

    // epilogue: + conn term, relu, store
    #pragma unroll
    for (int i = 0; i < 8; ++i) {
        int gr = rowBase + r4 + ((i < 4) ? i : (60 + i));
        if (gr >= N) continue;
        float s1 = __ldg(sv + gr), t1 = __ldg(tv + gr);
        float o[8];
        #pragma unroll
        for (int j = 0; j < 4; ++j) {
            float2 v = up2(acc[i][j]);
            o[2 * j] = v.x; o[2 * j + 1] = v.y;
        }
        #pragma unroll
        for (int jj = 0; jj < 8; ++jj) {
            int col = (jj < 4) ? (c4 + jj) : (c4 + 60 + jj);
            float c = o[jj] + s1 * __ldg(th1 + col * 2) + t1 * __ldg(th1 + col * 2 + 1);
            o[jj] = fmaxf(c, 0.0f);
        }
        *reinterpret_cast<float4*>(g_mu + (size_t)gr * 128 + c4) =
            make_float4(o[0], o[1], o[2], o[3]);
        *reinterpret_cast<float4*>(g_mu + (size_t)gr * 128 + c4 + 64) =
            make_float4(o[4], o[5], o[6], o[7]);
    }
}

// ---------------------------------------------------------------------------
// Stage C: mu' = [mu ; relu(deg*mu - nb)] @ h_theta^T   (K=256, 4 stages)
// smem: As 32 KB + Bs 32 KB = 64 KB
// ---------------------------------------------------------------------------
__global__ void __launch_bounds__(256, 2)
mup_kernel(int N) {
    extern __shared__ float sm[];
    float* As = sm;                 // 64*128
    float* Bs = sm + 64 * 128;      // 64*128
    int tid = threadIdx.x;
    int lane = tid & 31, w = tid >> 5;
    int rowBase = blockIdx.x * 128;
    int r4 = (tid >> 4) * 4, c4 = (tid & 15) * 4;
    unsigned long long acc[8][4] = {};

    #pragma unroll
    for (int s = 0; s < 4; ++s) {
        if (s) __syncthreads();
        if (s < 2) {
            loadA_plain(As, g_mu, rowBase, N, s, lane, w);
        } else {
            int h = s - 2;
            #pragma unroll
            for (int rb = 0; rb < 4; ++rb) {
                int r = rb * 32 + lane;
                int gr = rowBase + r;
                bool ok = gr < N;
                float dg = ok ? g_deg[gr] : 0.0f;
                #pragma unroll
                for (int cc = 0; cc < 2; ++cc) {
                    int k4 = w + 8 * cc;
                    float4 m = ok ? __ldg(reinterpret_cast<const float4*>(g_mu + (size_t)gr * 128) + 16 * h + k4)
                                  : make_float4(0.f, 0.f, 0.f, 0.f);
                    float4 nb = ok ? __ldg(reinterpret_cast<const float4*>(g_nb + (size_t)gr * 128) + 16 * h + k4)
                                   : make_float4(0.f, 0.f, 0.f, 0.f);
                    int kb = k4 * 4;
                    As[(kb + 0) * 128 + r] = fmaxf(dg * m.x - nb.x, 0.0f);
                    As[(kb + 1) * 128 + r] = fmaxf(dg * m.y - nb.y, 0.0f);
                    As[(kb + 2) * 128 + r] = fmaxf(dg * m.z - nb.z, 0.0f);
                    As[(kb + 3) * 128 + r] = fmaxf(dg * m.w - nb.w, 0.0f);
                }
            }
        }
        load_B64(Bs, g_Bh + (size_t)s * 64 * 128, tid);
        __syncthreads();
        mma64(As, Bs, r4, c4, acc);
    }
    __syncthreads();  // smem free for reduction reuse

    // epilogue: store mu' and reduce column sums
    float colp[8] = {0.f, 0.f, 0.f, 0.f, 0.f, 0.f, 0.f, 0.f};
    #pragma unroll
    for (int i = 0; i < 8; ++i) {
        int gr = rowBase + r4 + ((i < 4) ? i : (60 + i));
        float o[8];
        #pragma unroll
        for (int j = 0; j < 4; ++j) {
            float2 v = up2(acc[i][j]);
            o[2 * j] = v.x; o[2 * j + 1] = v.y;
        }
        #pragma unroll
        for (int jj = 0; jj < 8; ++jj) colp[jj] += o[jj];  // padded rows are 0
        if (gr < N) {
            *reinterpret_cast<float4*>(g_mup + (size_t)gr * 128 + c4) =
                make_float4(o[0], o[1], o[2], o[3]);
            *reinterpret_cast<float4*>(g_mup + (size_t)gr * 128 + c4 + 64) =
                make_float4(o[4], o[5], o[6], o[7]);
        }
    }
    float* part = sm;  // reuse: 16 x 128
    int ty = tid >> 4;
    #pragma unroll
    for (int jj = 0; jj < 8; ++jj) {
        int col = (jj < 4) ? (c4 + jj) : (c4 + 60 + jj);
        part[ty * 128 + col] = colp[jj];
    }
    __syncthreads();
    if (tid < 128) {
        float s = 0.0f;
        #pragma unroll
        for (int t = 0; t < 16; ++t) s += part[t * 128 + tid];
        atomicAdd(&g_summu[tid], s);
    }
}

// ---------------------------------------------------------------------------
// Q head: c_up = sum_p relu((theta4 @ sum_mu')[p]) * theta3[p]   (one block)
// ---------------------------------------------------------------------------
__global__ void qhead_kernel(const float* __restrict__ th4,
                             const float* __restrict__ th3) {
    __shared__ float svv[128];
    __shared__ float rbuf[4];
    int tid = threadIdx.x;
    svv[tid] = g_summu[tid];
    __syncthreads();
    float up = 0.0f;
    #pragma unroll 4
    for (int q = 0; q < 128; ++q) up += th4[tid * 128 + q] * svv[q];
    float v = fmaxf(up, 0.0f) * th3[tid];
    #pragma unroll
    for (int o = 16; o; o >>= 1) v += __shfl_xor_sync(0xFFFFFFFFu, v, o);
    if ((tid & 31) == 0) rbuf[tid >> 5] = v;
    __syncthreads();
    if (tid == 0) g_cup = rbuf[0] + rbuf[1] + rbuf[2] + rbuf[3];
}

// ---------------------------------------------------------------------------
// Stage E: out[v] = c_up + sum_j relu((mu' @ theta5^T)[v,j]) * theta3[128+j]
// smem: As 32 KB + Bs 64 KB = 96 KB
// ---------------------------------------------------------------------------
__global__ void __launch_bounds__(256, 2)
out_kernel(const float* __restrict__ th3, float* __restrict__ out, int N) {
    extern __shared__ float sm[];
    float* As = sm;
    float* Bs = sm + 64 * 128;
    int tid = threadIdx.x;
    int lane = tid & 31, w = tid >> 5;
    int rowBase = blockIdx.x * 128;
    int r4 = (tid >> 4) * 4, c4 = (tid & 15) * 4;
    unsigned long long acc[8][4] = {};

    load_B128(Bs, g_B5, tid);
    loadA_plain(As, g_mup, rowBase, N, 0, lane, w);
    __syncthreads();
    mma64(As, Bs, r4, c4, acc);
    __syncthreads();
    loadA_plain(As, g_mup, rowBase, N, 1, lane, w);
    __syncthreads();
    mma64(As, Bs + 64 * 128, r4, c4, acc);
    __syncthreads();  // smem free for reduction reuse

    // per-thread weighted relu row partials
    float rowp[8];
    #pragma unroll
    for (int i = 0; i < 8; ++i) {
        float rp = 0.0f;
        #pragma unroll
        for (int j = 0; j < 4; ++j) {
            float2 v = up2(acc[i][j]);
            int cbase = (j < 2) ? (c4 + 2 * j) : (c4 + 64 + 2 * (j - 2));
            rp += fmaxf(v.x, 0.0f) * __ldg(th3 + 128 + cbase);
            rp += fmaxf(v.y, 0.0f) * __ldg(th3 + 128 + cbase + 1);
        }
        rowp[i] = rp;
    }
    float* red = sm;  // 16 x 129 (conflict-free stride)
    int tx = tid & 15;
    #pragma unroll
    for (int i = 0; i < 8; ++i) {
        int row = r4 + ((i < 4) ? i : (60 + i));
        red[tx * 129 + row] = rowp[i];
    }
    __syncthreads();
    if (tid < 128) {
        float s = 0.0f;
        #pragma unroll
        for (int t = 0; t < 16; ++t) s += red[t * 129 + tid];
        int gr = rowBase + tid;
        if (gr < N) out[gr] = g_cup + s;
    }
}

// ---------------------------------------------------------------------------
// Launch
// ---------------------------------------------------------------------------
extern "C" void kernel_launch(void* const* d_in, const int* in_sizes, int n_in,
                              void* d_out, int out_size) {
    const float* s_v  = (const float*)d_in[0];
    const float* t_v  = (const float*)d_in[1];
    const float* x    = (const float*)d_in[2];
    const int*   esrc = (const int*)  d_in[3];
    const int*   edst = (const int*)  d_in[4];
    const float* th1  = (const float*)d_in[5];
    const float* th2  = (const float*)d_in[6];
    const float* th3  = (const float*)d_in[7];
    const float* th4  = (const float*)d_in[8];
    const float* th5  = (const float*)d_in[9];
    const float* hth  = (const float*)d_in[10];
    float* out = (float*)d_out;

    int N = in_sizes[0];
    int E = in_sizes[3];
    int tiles = (N + 127) / 128;
    int smem96 = (64 * 128 + 128 * 128) * (int)sizeof(float);  // 96 KB
    int smem64 = (64 * 128 + 64 * 128) * (int)sizeof(float);   // 64 KB

    cudaFuncSetAttribute(mu_kernel,  cudaFuncAttributeMaxDynamicSharedMemorySize, smem96);
    cudaFuncSetAttribute(mup_kernel, cudaFuncAttributeMaxDynamicSharedMemorySize, smem64);
    cudaFuncSetAttribute(out_kernel, cudaFuncAttributeMaxDynamicSharedMemorySize, smem96);

    prep_kernel<<<64, 256>>>(th2, th5, hth);
    zero_kernel<<<4096, 256>>>(N);
    norm_kernel<<<(N + 7) / 8, 256>>>(x, N);
    mu_kernel<<<tiles, 256, smem96>>>(x, s_v, t_v, th1, N);
    edge_kernel<<<8192, 256>>>(esrc, edst, E);
    mup_kernel<<<tiles, 256, smem64>>>(N);
    qhead_kernel<<<1, 128>>>(th4, th3);
    out_kernel<<<tiles, 256, smem96>>>(th3, out, N);
}